// round 2
// baseline (speedup 1.0000x reference)
#include <cuda_runtime.h>
#include <math.h>

// Problem constants
#define N_NODES   10000
#define N_EDGES   160000
#define NE_TOT    170000        // edges + self loops
#define IN_DIM    128
#define HID       16
#define HEADS     50
#define HC        800           // HEADS*HID
#define OUT_DIM   10
#define N_GRAPHS  8
#define NEG_SLOPE 0.2f

// Scratch (device globals: no allocation allowed)
__device__ float g_xp[N_NODES * HC];          // 32 MB projected features
__device__ float g_as[N_NODES * HEADS];       // alpha_src dot
__device__ float g_ad[N_NODES * HEADS];       // alpha_dst dot
__device__ float g_logits[NE_TOT * HEADS];    // 34 MB, reused as exp values
__device__ float g_m[N_NODES * HEADS];        // segment max
__device__ float g_denom[N_NODES * HEADS];    // segment sum of exp
__device__ float g_agg[N_NODES * HID];        // head-summed aggregate
__device__ float g_gsum[N_GRAPHS * HID];
__device__ float g_gcnt[N_GRAPHS];

__device__ __forceinline__ float atomicMaxF(float* addr, float val) {
    if (val >= 0.0f)
        return __int_as_float(atomicMax((int*)addr, __float_as_int(val)));
    else
        return __uint_as_float(atomicMin((unsigned int*)addr, __float_as_uint(val)));
}

// ---------------- init ----------------
__global__ void k_init() {
    int i = blockIdx.x * blockDim.x + threadIdx.x;
    int stride = gridDim.x * blockDim.x;
    for (int j = i; j < N_NODES * HEADS; j += stride) {
        g_m[j] = -INFINITY;
        g_denom[j] = 0.0f;
    }
    for (int j = i; j < N_NODES * HID; j += stride) g_agg[j] = 0.0f;
    if (i < N_GRAPHS * HID) g_gsum[i] = 0.0f;
    if (i < N_GRAPHS) g_gcnt[i] = 0.0f;
}

// ---------------- GEMM: xp = x @ W  (MxK @ KxN, M=10000, K=128, N=800) ----
#define BM 64
#define BN 64
#define BK 32
__global__ void k_gemm(const float* __restrict__ A, const float* __restrict__ B) {
    __shared__ float As[BK][BM + 1];
    __shared__ float Bs[BK][BN];
    int tid = threadIdx.x;                 // 256 threads
    int tx = tid & 15;                     // 0..15 col group
    int ty = tid >> 4;                     // 0..15 row group
    int rowBase = blockIdx.y * BM;
    int colBase = blockIdx.x * BN;

    float acc[4][4] = {};

    for (int k0 = 0; k0 < IN_DIM; k0 += BK) {
        // load A tile 64x32 (transposed into smem)
#pragma unroll
        for (int i = 0; i < 8; i++) {
            int idx = i * 256 + tid;
            int r = idx >> 5, c = idx & 31;
            int grow = rowBase + r;
            As[c][r] = (grow < N_NODES) ? A[grow * IN_DIM + k0 + c] : 0.0f;
        }
        // load B tile 32x64
#pragma unroll
        for (int i = 0; i < 8; i++) {
            int idx = i * 256 + tid;
            int r = idx >> 6, c = idx & 63;
            int gcol = colBase + c;
            Bs[r][c] = (gcol < HC) ? B[(k0 + r) * HC + gcol] : 0.0f;
        }
        __syncthreads();
#pragma unroll
        for (int kk = 0; kk < BK; kk++) {
            float a[4], b[4];
#pragma unroll
            for (int i = 0; i < 4; i++) a[i] = As[kk][ty * 4 + i];
#pragma unroll
            for (int j = 0; j < 4; j++) b[j] = Bs[kk][tx * 4 + j];
#pragma unroll
            for (int i = 0; i < 4; i++)
#pragma unroll
                for (int j = 0; j < 4; j++) acc[i][j] += a[i] * b[j];
        }
        __syncthreads();
    }
#pragma unroll
    for (int i = 0; i < 4; i++) {
        int row = rowBase + ty * 4 + i;
        if (row >= N_NODES) continue;
#pragma unroll
        for (int j = 0; j < 4; j++) {
            int col = colBase + tx * 4 + j;
            if (col < HC) g_xp[row * HC + col] = acc[i][j];
        }
    }
}

// ---------------- per-(node,head) attention dots ----------------
__global__ void k_alphas(const float* __restrict__ a_src, const float* __restrict__ a_dst) {
    int i = blockIdx.x * blockDim.x + threadIdx.x;
    if (i >= N_NODES * HEADS) return;
    int h = i % HEADS;
    const float* xr = g_xp + (i / HEADS) * HC + h * HID;
    const float* as = a_src + h * HID;
    const float* ad = a_dst + h * HID;
    float s = 0.0f, d = 0.0f;
#pragma unroll
    for (int c = 0; c < HID; c++) {
        float v = xr[c];
        s += v * as[c];
        d += v * ad[c];
    }
    g_as[i] = s;
    g_ad[i] = d;
}

// ---------------- pass 1: logits + segment max ----------------
__global__ void k_logits(const int* __restrict__ ei) {
    int i = blockIdx.x * blockDim.x + threadIdx.x;
    if (i >= NE_TOT * HEADS) return;
    int e = i / HEADS;
    int h = i - e * HEADS;
    int src, dst;
    if (e < N_EDGES) {
        src = ei[e];
        dst = ei[N_EDGES + e];
    } else {
        src = dst = e - N_EDGES;
    }
    float v = g_as[src * HEADS + h] + g_ad[dst * HEADS + h];
    v = (v > 0.0f) ? v : NEG_SLOPE * v;
    g_logits[i] = v;
    atomicMaxF(&g_m[dst * HEADS + h], v);
}

// ---------------- pass 2: exp + segment sum ----------------
__global__ void k_expsum(const int* __restrict__ ei) {
    int i = blockIdx.x * blockDim.x + threadIdx.x;
    if (i >= NE_TOT * HEADS) return;
    int e = i / HEADS;
    int h = i - e * HEADS;
    int dst = (e < N_EDGES) ? ei[N_EDGES + e] : (e - N_EDGES);
    float ex = __expf(g_logits[i] - g_m[dst * HEADS + h]);
    g_logits[i] = ex;
    atomicAdd(&g_denom[dst * HEADS + h], ex);
}

// ---------------- pass 3: weighted aggregate (head-reduced per edge) ------
#define EPB 16   // edges per block (256 threads, 16 lanes/edge)
__global__ void k_aggregate(const int* __restrict__ ei) {
    __shared__ int ssrc[EPB];
    __shared__ int sdst[EPB];
    __shared__ float salpha[EPB][HEADS];
    int tid = threadIdx.x;
    int eBase = blockIdx.x * EPB;

    if (tid < EPB) {
        int e = eBase + tid;
        int src = 0, dst = 0;
        if (e < NE_TOT) {
            if (e < N_EDGES) {
                src = ei[e];
                dst = ei[N_EDGES + e];
            } else {
                src = dst = e - N_EDGES;
            }
        }
        ssrc[tid] = src;
        sdst[tid] = dst;
    }
    __syncthreads();

    for (int idx = tid; idx < EPB * HEADS; idx += blockDim.x) {
        int le = idx / HEADS;
        int h = idx - le * HEADS;
        int e = eBase + le;
        float a = 0.0f;
        if (e < NE_TOT)
            a = g_logits[e * HEADS + h] / g_denom[sdst[le] * HEADS + h];
        salpha[le][h] = a;
    }
    __syncthreads();

    int le = tid >> 4;       // local edge
    int c = tid & 15;        // channel
    int e = eBase + le;
    if (e >= NE_TOT) return;
    const float* xr = g_xp + ssrc[le] * HC + c;
    float acc = 0.0f;
#pragma unroll
    for (int h = 0; h < HEADS; h++) {
        acc += salpha[le][h] * xr[h * HID];
    }
    atomicAdd(&g_agg[sdst[le] * HID + c], acc);
}

// ---------------- finalize + graph pool ----------------
__global__ void k_pool(const int* __restrict__ batch, const float* __restrict__ bias) {
    __shared__ float ssum[N_GRAPHS * HID];
    __shared__ float scnt[N_GRAPHS];
    int t = threadIdx.x;
    if (t < N_GRAPHS * HID) ssum[t] = 0.0f;
    if (t < N_GRAPHS) scnt[t] = 0.0f;
    __syncthreads();
    int i = blockIdx.x * blockDim.x + t;
    if (i < N_NODES * HID) {
        int n = i >> 4, c = i & 15;
        float v = g_agg[i] * (1.0f / (float)HEADS) + bias[c];
        int g = batch[n];
        atomicAdd(&ssum[g * HID + c], v);
        if (c == 0) atomicAdd(&scnt[g], 1.0f);
    }
    __syncthreads();
    if (t < N_GRAPHS * HID) atomicAdd(&g_gsum[t], ssum[t]);
    if (t < N_GRAPHS) atomicAdd(&g_gcnt[t], scnt[t]);
}

// ---------------- final FC ----------------
__global__ void k_fc(const float* __restrict__ fc_w, const float* __restrict__ fc_b,
                     float* __restrict__ out) {
    int i = threadIdx.x;
    if (i >= N_GRAPHS * OUT_DIM) return;
    int g = i / OUT_DIM, o = i - g * OUT_DIM;
    float cnt = fmaxf(g_gcnt[g], 1.0f);
    float inv = 1.0f / cnt;
    float s = fc_b[o];
#pragma unroll
    for (int c = 0; c < HID; c++)
        s += (g_gsum[g * HID + c] * inv) * fc_w[c * OUT_DIM + o];
    out[i] = s;
}

extern "C" void kernel_launch(void* const* d_in, const int* in_sizes, int n_in,
                              void* d_out, int out_size) {
    const float* x = nullptr;
    const int* ei = nullptr;       // int32 (JAX x64 disabled)
    const int* batch = nullptr;    // int32
    const float* W = nullptr;
    const float* a_src = nullptr;
    const float* a_dst = nullptr;
    const float* bias = nullptr;
    const float* fc_w = nullptr;
    const float* fc_b = nullptr;

    for (int i = 0; i < n_in; i++) {
        int s = in_sizes[i];
        switch (s) {
            case N_NODES * IN_DIM:  x = (const float*)d_in[i]; break;       // 1280000
            case 2 * N_EDGES:       ei = (const int*)d_in[i]; break;        // 320000
            case N_NODES:           batch = (const int*)d_in[i]; break;     // 10000
            case IN_DIM * HC:       W = (const float*)d_in[i]; break;       // 102400
            case HEADS * HID:                                                // 800 (x2)
                if (!a_src) a_src = (const float*)d_in[i];
                else a_dst = (const float*)d_in[i];
                break;
            case HID:               bias = (const float*)d_in[i]; break;    // 16
            case HID * OUT_DIM:     fc_w = (const float*)d_in[i]; break;    // 160
            case OUT_DIM:           fc_b = (const float*)d_in[i]; break;    // 10
            default: break; // num_graphs scalar
        }
    }
    float* out = (float*)d_out;

    k_init<<<2048, 256>>>();
    dim3 ggrid((HC + BN - 1) / BN, (N_NODES + BM - 1) / BM);
    k_gemm<<<ggrid, 256>>>(x, W);
    k_alphas<<<(N_NODES * HEADS + 255) / 256, 256>>>(a_src, a_dst);
    k_logits<<<(NE_TOT * HEADS + 255) / 256, 256>>>(ei);
    k_expsum<<<(NE_TOT * HEADS + 255) / 256, 256>>>(ei);
    k_aggregate<<<(NE_TOT + EPB - 1) / EPB, 256>>>(ei);
    k_pool<<<(N_NODES * HID + 255) / 256, 256>>>(batch, bias);
    k_fc<<<1, 128>>>(fc_w, fc_b, out);
}

// round 3
// speedup vs baseline: 1.4145x; 1.4145x over previous
#include <cuda_runtime.h>
#include <math.h>
#include <stdint.h>

// Problem constants
#define N_NODES   10000
#define N_EDGES   160000
#define NE_TOT    170000        // edges + self loops
#define IN_DIM    128
#define HID       16
#define HEADS     50
#define HC        800           // HEADS*HID
#define OUT_DIM   10
#define N_GRAPHS  8
#define NEG_SLOPE 0.2f

// Scratch (device globals: no allocation allowed)
__device__ float g_xp[N_NODES * HC];          // 32 MB projected features
__device__ float g_as[N_NODES * HEADS];       // alpha_src dot
__device__ float g_ad[N_NODES * HEADS];       // alpha_dst dot
__device__ float g_denom[N_NODES * HEADS];    // segment sum of exp(logit)
__device__ float g_agg[N_NODES * HID];        // head-summed aggregate
__device__ float g_gsum[N_GRAPHS * HID];
__device__ float g_gcnt[N_GRAPHS];

// ---------------- init ----------------
__global__ void k_init() {
    int i = blockIdx.x * blockDim.x + threadIdx.x;
    int stride = gridDim.x * blockDim.x;
    for (int j = i; j < N_NODES * HEADS; j += stride) g_denom[j] = 0.0f;
    for (int j = i; j < N_NODES * HID; j += stride) g_agg[j] = 0.0f;
    if (i < N_GRAPHS * HID) g_gsum[i] = 0.0f;
    if (i < N_GRAPHS) g_gcnt[i] = 0.0f;
}

// ---------------- tf32 tensor-core GEMM: xp = x @ W ----------------
// M=10000, K=128, N=800.  Block tile 128x64, K-chunk 32, 8 warps (4x2).
#define GBM 128
#define GBN 64
#define GBK 32

__device__ __forceinline__ uint32_t f2tf32(float f) {
    uint32_t r;
    asm("cvt.rna.tf32.f32 %0, %1;" : "=r"(r) : "f"(f));
    return r;
}

__device__ __forceinline__ void mma_tf32(float c[4], const uint32_t a[4], const uint32_t b[2]) {
    asm volatile(
        "mma.sync.aligned.m16n8k8.row.col.f32.tf32.tf32.f32 "
        "{%0,%1,%2,%3}, {%4,%5,%6,%7}, {%8,%9}, {%0,%1,%2,%3};"
        : "+f"(c[0]), "+f"(c[1]), "+f"(c[2]), "+f"(c[3])
        : "r"(a[0]), "r"(a[1]), "r"(a[2]), "r"(a[3]), "r"(b[0]), "r"(b[1]));
}

__global__ void k_gemm_tf32(const float* __restrict__ A, const float* __restrict__ B) {
    __shared__ float As[GBM][GBK + 4];
    __shared__ float Bs[GBK][GBN + 4];
    int tid = threadIdx.x;            // 256 threads
    int warp = tid >> 5, lane = tid & 31;
    int wm = warp >> 1;               // 0..3 : 32-row strip
    int wn = warp & 1;                // 0..1 : 32-col strip
    int grp = lane >> 2;              // 0..7
    int thr = lane & 3;               // 0..3
    int rowBase = blockIdx.y * GBM;
    int colBase = blockIdx.x * GBN;

    float c[2][4][4];
#pragma unroll
    for (int mt = 0; mt < 2; mt++)
#pragma unroll
        for (int nt = 0; nt < 4; nt++)
#pragma unroll
            for (int r = 0; r < 4; r++) c[mt][nt][r] = 0.0f;

    for (int k0 = 0; k0 < IN_DIM; k0 += GBK) {
        // A tile: 128x32 = 4096 floats, 16 per thread
#pragma unroll
        for (int i = 0; i < 16; i++) {
            int idx = i * 256 + tid;
            int r = idx >> 5, cc = idx & 31;
            int gr = rowBase + r;
            As[r][cc] = (gr < N_NODES) ? A[gr * IN_DIM + k0 + cc] : 0.0f;
        }
        // B tile: 32x64 = 2048 floats, 8 per thread
#pragma unroll
        for (int i = 0; i < 8; i++) {
            int idx = i * 256 + tid;
            int r = idx >> 6, cc = idx & 63;
            int gc = colBase + cc;
            Bs[r][cc] = (gc < HC) ? B[(k0 + r) * HC + gc] : 0.0f;
        }
        __syncthreads();
#pragma unroll
        for (int kk = 0; kk < GBK; kk += 8) {
            uint32_t af[2][4], bf[4][2];
#pragma unroll
            for (int mt = 0; mt < 2; mt++) {
                int rb = wm * 32 + mt * 16;
                af[mt][0] = f2tf32(As[rb + grp][kk + thr]);
                af[mt][1] = f2tf32(As[rb + grp + 8][kk + thr]);
                af[mt][2] = f2tf32(As[rb + grp][kk + thr + 4]);
                af[mt][3] = f2tf32(As[rb + grp + 8][kk + thr + 4]);
            }
#pragma unroll
            for (int nt = 0; nt < 4; nt++) {
                int cb = wn * 32 + nt * 8;
                bf[nt][0] = f2tf32(Bs[kk + thr][cb + grp]);
                bf[nt][1] = f2tf32(Bs[kk + thr + 4][cb + grp]);
            }
#pragma unroll
            for (int mt = 0; mt < 2; mt++)
#pragma unroll
                for (int nt = 0; nt < 4; nt++)
                    mma_tf32(c[mt][nt], af[mt], bf[nt]);
        }
        __syncthreads();
    }

    // store
#pragma unroll
    for (int mt = 0; mt < 2; mt++) {
#pragma unroll
        for (int nt = 0; nt < 4; nt++) {
            int row0 = rowBase + wm * 32 + mt * 16 + grp;
            int col = colBase + wn * 32 + nt * 8 + thr * 2;
            if (col + 1 < HC) {
                if (row0 < N_NODES) {
                    g_xp[row0 * HC + col]     = c[mt][nt][0];
                    g_xp[row0 * HC + col + 1] = c[mt][nt][1];
                }
                if (row0 + 8 < N_NODES) {
                    g_xp[(row0 + 8) * HC + col]     = c[mt][nt][2];
                    g_xp[(row0 + 8) * HC + col + 1] = c[mt][nt][3];
                }
            }
        }
    }
}

// ---------------- per-(node,head) attention dots ----------------
__global__ void k_alphas(const float* __restrict__ a_src, const float* __restrict__ a_dst) {
    int i = blockIdx.x * blockDim.x + threadIdx.x;
    if (i >= N_NODES * HEADS) return;
    int h = i % HEADS;
    const float* xr = g_xp + (i / HEADS) * HC + h * HID;
    const float* as = a_src + h * HID;
    const float* ad = a_dst + h * HID;
    float s = 0.0f, d = 0.0f;
#pragma unroll
    for (int c = 0; c < HID; c++) {
        float v = xr[c];
        s += v * as[c];
        d += v * ad[c];
    }
    g_as[i] = s;
    g_ad[i] = d;
}

// ---------------- fused logits+exp+denom (no max pass, no logits buffer) --
__global__ void k_denom(const int* __restrict__ ei) {
    int i = blockIdx.x * blockDim.x + threadIdx.x;
    if (i >= NE_TOT * HEADS) return;
    int e = i / HEADS;
    int h = i - e * HEADS;
    int src, dst;
    if (e < N_EDGES) {
        src = ei[e];
        dst = ei[N_EDGES + e];
    } else {
        src = dst = e - N_EDGES;
    }
    float v = g_as[src * HEADS + h] + g_ad[dst * HEADS + h];
    v = (v > 0.0f) ? v : NEG_SLOPE * v;
    atomicAdd(&g_denom[dst * HEADS + h], __expf(v));
}

// ---------------- weighted aggregate (alpha recomputed, head-reduced) -----
#define EPB 16   // edges per block (256 threads, 16 lanes/edge)
__global__ void k_aggregate(const int* __restrict__ ei) {
    __shared__ int ssrc[EPB];
    __shared__ int sdst[EPB];
    __shared__ float salpha[EPB][HEADS];
    int tid = threadIdx.x;
    int eBase = blockIdx.x * EPB;

    if (tid < EPB) {
        int e = eBase + tid;
        int src = 0, dst = 0;
        if (e < NE_TOT) {
            if (e < N_EDGES) {
                src = ei[e];
                dst = ei[N_EDGES + e];
            } else {
                src = dst = e - N_EDGES;
            }
        }
        ssrc[tid] = src;
        sdst[tid] = dst;
    }
    __syncthreads();

    for (int idx = tid; idx < EPB * HEADS; idx += blockDim.x) {
        int le = idx / HEADS;
        int h = idx - le * HEADS;
        int e = eBase + le;
        float a = 0.0f;
        if (e < NE_TOT) {
            int src = ssrc[le], dst = sdst[le];
            float v = g_as[src * HEADS + h] + g_ad[dst * HEADS + h];
            v = (v > 0.0f) ? v : NEG_SLOPE * v;
            a = __fdividef(__expf(v), g_denom[dst * HEADS + h]);
        }
        salpha[le][h] = a;
    }
    __syncthreads();

    int le = tid >> 4;       // local edge
    int c = tid & 15;        // channel
    int e = eBase + le;
    if (e >= NE_TOT) return;
    const float* xr = g_xp + ssrc[le] * HC + c;
    float acc = 0.0f;
#pragma unroll
    for (int h = 0; h < HEADS; h++) {
        acc += salpha[le][h] * xr[h * HID];
    }
    atomicAdd(&g_agg[sdst[le] * HID + c], acc);
}

// ---------------- finalize + graph pool ----------------
__global__ void k_pool(const int* __restrict__ batch, const float* __restrict__ bias) {
    __shared__ float ssum[N_GRAPHS * HID];
    __shared__ float scnt[N_GRAPHS];
    int t = threadIdx.x;
    if (t < N_GRAPHS * HID) ssum[t] = 0.0f;
    if (t < N_GRAPHS) scnt[t] = 0.0f;
    __syncthreads();
    int i = blockIdx.x * blockDim.x + t;
    if (i < N_NODES * HID) {
        int n = i >> 4, c = i & 15;
        float v = g_agg[i] * (1.0f / (float)HEADS) + bias[c];
        int g = batch[n];
        atomicAdd(&ssum[g * HID + c], v);
        if (c == 0) atomicAdd(&scnt[g], 1.0f);
    }
    __syncthreads();
    if (t < N_GRAPHS * HID) atomicAdd(&g_gsum[t], ssum[t]);
    if (t < N_GRAPHS) atomicAdd(&g_gcnt[t], scnt[t]);
}

// ---------------- final FC ----------------
__global__ void k_fc(const float* __restrict__ fc_w, const float* __restrict__ fc_b,
                     float* __restrict__ out) {
    int i = threadIdx.x;
    if (i >= N_GRAPHS * OUT_DIM) return;
    int g = i / OUT_DIM, o = i - g * OUT_DIM;
    float cnt = fmaxf(g_gcnt[g], 1.0f);
    float inv = 1.0f / cnt;
    float s = fc_b[o];
#pragma unroll
    for (int c = 0; c < HID; c++)
        s += (g_gsum[g * HID + c] * inv) * fc_w[c * OUT_DIM + o];
    out[i] = s;
}

extern "C" void kernel_launch(void* const* d_in, const int* in_sizes, int n_in,
                              void* d_out, int out_size) {
    const float* x = nullptr;
    const int* ei = nullptr;       // int32 (JAX x64 disabled)
    const int* batch = nullptr;    // int32
    const float* W = nullptr;
    const float* a_src = nullptr;
    const float* a_dst = nullptr;
    const float* bias = nullptr;
    const float* fc_w = nullptr;
    const float* fc_b = nullptr;

    for (int i = 0; i < n_in; i++) {
        int s = in_sizes[i];
        switch (s) {
            case N_NODES * IN_DIM:  x = (const float*)d_in[i]; break;       // 1280000
            case 2 * N_EDGES:       ei = (const int*)d_in[i]; break;        // 320000
            case N_NODES:           batch = (const int*)d_in[i]; break;     // 10000
            case IN_DIM * HC:       W = (const float*)d_in[i]; break;       // 102400
            case HEADS * HID:                                                // 800 (x2)
                if (!a_src) a_src = (const float*)d_in[i];
                else a_dst = (const float*)d_in[i];
                break;
            case HID:               bias = (const float*)d_in[i]; break;    // 16
            case HID * OUT_DIM:     fc_w = (const float*)d_in[i]; break;    // 160
            case OUT_DIM:           fc_b = (const float*)d_in[i]; break;    // 10
            default: break; // num_graphs scalar
        }
    }
    float* out = (float*)d_out;

    k_init<<<2048, 256>>>();
    dim3 ggrid((HC + GBN - 1) / GBN, (N_NODES + GBM - 1) / GBM);
    k_gemm_tf32<<<ggrid, 256>>>(x, W);
    k_alphas<<<(N_NODES * HEADS + 255) / 256, 256>>>(a_src, a_dst);
    k_denom<<<(NE_TOT * HEADS + 255) / 256, 256>>>(ei);
    k_aggregate<<<(NE_TOT + EPB - 1) / EPB, 256>>>(ei);
    k_pool<<<(N_NODES * HID + 255) / 256, 256>>>(batch, bias);
    k_fc<<<1, 128>>>(fc_w, fc_b, out);
}